// round 15
// baseline (speedup 1.0000x reference)
#include <cuda_runtime.h>
#include <cuda_fp16.h>
#include <cuda_bf16.h>
#include <math.h>
#include <float.h>
#include <stdint.h>

#define N_ROWS 8192
#define M_ROWS 16384
#define D_DIM  512
#define K_TOP  10
#define K_CAND 16
#define EPSF   1e-8f

// ================= helpers =================
__device__ __forceinline__ uint32_t smem_u32(const void* p) {
    uint32_t a;
    asm("{ .reg .u64 t; cvta.to.shared.u64 t, %1; cvt.u32.u64 %0, t; }" : "=r"(a) : "l"(p));
    return a;
}
#define CP_ASYNC16(dst, src) asm volatile("cp.async.cg.shared.global [%0], [%1], 16;" :: "r"(dst), "l"(src) : "memory")
#define CP_COMMIT()          asm volatile("cp.async.commit_group;" ::: "memory")
#define CP_WAIT(n)           asm volatile("cp.async.wait_group %0;" :: "n"(n) : "memory")

#define LDSM_X4(r0, r1, r2, r3, a) \
    asm volatile("ldmatrix.sync.aligned.m8n8.x4.shared.b16 {%0,%1,%2,%3}, [%4];" \
        : "=r"(r0), "=r"(r1), "=r"(r2), "=r"(r3) : "r"(a))

// fp16 in, fp16 accumulate: D/C are 2x half2 regs
#define MMA16816_F16(c0, c1, a0, a1, a2, a3, b0, b1) \
    asm volatile("mma.sync.aligned.m16n8k16.row.col.f16.f16.f16.f16 " \
        "{%0,%1}, {%2,%3,%4,%5}, {%6,%7}, {%0,%1};" \
        : "+r"(c0), "+r"(c1) \
        : "r"(a0), "r"(a1), "r"(a2), "r"(a3), "r"(b0), "r"(b1))

// monotone u16 key from float (via bf16): order-preserving, smaller = nearer
__device__ __forceinline__ uint32_t score_key(float s) {
    uint16_t bits = __bfloat16_as_ushort(__float2bfloat16(s));
    uint16_t key = (bits & 0x8000) ? (uint16_t)~bits : (uint16_t)(bits | 0x8000);
    return (uint32_t)key;
}

// ================= device scratch =================
__device__ uint16_t g_key[(size_t)N_ROWS * (size_t)M_ROWS];  // 256 MB u16 key matrix
__device__ __half g_ah[(size_t)N_ROWS * D_DIM];
__device__ __half g_bh[(size_t)M_ROWS * D_DIM];
__device__ float g_x2[N_ROWS];
__device__ float g_m2[M_ROWS];
__device__ float g_mean[N_ROWS];
__device__ int   g_idx0[N_ROWS];
__device__ int   g_cand[(size_t)N_ROWS * K_CAND];
__device__ float g_dmin;
__device__ float g_dmax;

// ================= fused: row sum-of-squares + fp32->fp16 convert =================
__global__ __launch_bounds__(128) void rowsumsq_conv(const float* __restrict__ src, int which) {
    float* dst = which ? g_m2 : g_x2;
    __half* hout = which ? g_bh : g_ah;
    int row = blockIdx.x;
    const float4* p = (const float4*)(src + (size_t)row * D_DIM);
    float4 v = p[threadIdx.x];

    __half2 h01 = __floats2half2_rn(v.x, v.y);
    __half2 h23 = __floats2half2_rn(v.z, v.w);
    __half2* ho = (__half2*)(hout + (size_t)row * D_DIM) + threadIdx.x * 2;
    ho[0] = h01; ho[1] = h23;

    float s = v.x * v.x + v.y * v.y + v.z * v.z + v.w * v.w;
    #pragma unroll
    for (int o = 16; o; o >>= 1) s += __shfl_down_sync(0xffffffffu, s, o);
    __shared__ float ws[4];
    if ((threadIdx.x & 31) == 0) ws[threadIdx.x >> 5] = s;
    __syncthreads();
    if (threadIdx.x == 0) dst[row] = ws[0] + ws[1] + ws[2] + ws[3];
}

// ================= fp16 HMMA GEMM (fp16 acc) -> u16 key matrix =================
// 128x128 CTA tile, BK=64, 128 threads = 4 warps (2m x 2n), warp tile 64x64.
// 2-stage double buffer -> 73.7 KB smem -> 3 CTAs/SM for cross-CTA overlap.
#define ROWB    144
#define SA_STG  (128 * ROWB)     // 18432
#define SB_STG  (128 * ROWB)     // 18432
#define SB_BASE (2 * SA_STG)
#define SM_TOT  (2 * SA_STG + 2 * SB_STG)  // 73728

__global__ void __launch_bounds__(128, 3) gemm_score_mma() {
    extern __shared__ __align__(128) uint8_t smem[];
    const uint32_t sbA = smem_u32(smem);
    const uint32_t sbB = sbA + SB_BASE;

    const int tid  = threadIdx.x;
    const int lane = tid & 31;
    const int wid  = tid >> 5;
    const int wm   = wid >> 1;          // 0..1 (64 rows each)
    const int wn   = wid & 1;           // 0..1 (64 cols each)
    const int bm   = blockIdx.y * 128;
    const int bn   = blockIdx.x * 128;

    // cp.async staging: rows have 8 x 16B chunks (128B data per row)
    const int rr = tid >> 3;            // 0..15
    const int kc = tid & 7;             // chunk 0..7
    const __half* gA = g_ah + (size_t)bm * D_DIM + kc * 8;
    const __half* gB = g_bh + (size_t)bn * D_DIM + kc * 8;

    const int lrow = (lane & 7) + ((lane >> 3) & 1) * 8;
    const int lcol = (lane >> 4) * 8;
    uint32_t aBase[4], bBase[4];
    #pragma unroll
    for (int mf = 0; mf < 4; mf++)
        aBase[mf] = sbA + (wm * 64 + mf * 16 + lrow) * ROWB + lcol * 2;
    #pragma unroll
    for (int np = 0; np < 4; np++)
        bBase[np] = sbB + (wn * 64 + np * 16 + lrow) * ROWB + lcol * 2;

    uint32_t acc[4][8][2];
    #pragma unroll
    for (int mf = 0; mf < 4; mf++)
        #pragma unroll
        for (int nf = 0; nf < 8; nf++) { acc[mf][nf][0] = 0u; acc[mf][nf][1] = 0u; }

    auto load_stage = [&](int kt, int buf) {
        const int koff = kt * 64;
        #pragma unroll
        for (int i = 0; i < 8; i++) {          // A: 128 rows
            int r = rr + i * 16;
            CP_ASYNC16(sbA + buf * SA_STG + r * ROWB + kc * 16,
                       gA + (size_t)r * D_DIM + koff);
        }
        #pragma unroll
        for (int i = 0; i < 8; i++) {          // B: 128 rows
            int r = rr + i * 16;
            CP_ASYNC16(sbB + buf * SB_STG + r * ROWB + kc * 16,
                       gB + (size_t)r * D_DIM + koff);
        }
    };

    load_stage(0, 0); CP_COMMIT();

    #pragma unroll 1
    for (int kt = 0; kt < 8; kt++) {
        const int buf = kt & 1;
        CP_WAIT(0);
        __syncthreads();

        if (kt + 1 < 8) {
            load_stage(kt + 1, buf ^ 1);
            CP_COMMIT();
        }

        const uint32_t ao = buf * SA_STG;
        const uint32_t bo = buf * SB_STG;

        #pragma unroll
        for (int ks = 0; ks < 4; ks++) {
            const int ko = ks * 32;
            uint32_t af[4][4], bf[4][4];
            #pragma unroll
            for (int mf = 0; mf < 4; mf++)
                LDSM_X4(af[mf][0], af[mf][1], af[mf][2], af[mf][3], aBase[mf] + ao + ko);
            #pragma unroll
            for (int np = 0; np < 4; np++)
                LDSM_X4(bf[np][0], bf[np][1], bf[np][2], bf[np][3], bBase[np] + bo + ko);

            #pragma unroll
            for (int mf = 0; mf < 4; mf++) {
                #pragma unroll
                for (int nf = 0; nf < 8; nf++) {
                    const int np = nf >> 1, o = nf & 1;
                    MMA16816_F16(acc[mf][nf][0], acc[mf][nf][1],
                                 af[mf][0], af[mf][1], af[mf][2], af[mf][3],
                                 bf[np][0 + o], bf[np][2 + o]);
                }
            }
        }
    }

    // epilogue: key = monotone_u16(m2 - 2*dot), packed 2 per u32
    const int q = lane >> 2, p = lane & 3;
    #pragma unroll
    for (int nf = 0; nf < 8; nf++) {
        const int cg = bn + wn * 64 + nf * 8 + p * 2;
        const float m20 = g_m2[cg], m21 = g_m2[cg + 1];
        #pragma unroll
        for (int mf = 0; mf < 4; mf++) {
            const int rg0 = bm + wm * 64 + mf * 16 + q;
            float2 lo = __half22float2(*(const __half2*)&acc[mf][nf][0]);
            float2 hi = __half22float2(*(const __half2*)&acc[mf][nf][1]);
            uint32_t k0 = score_key(m20 - 2.0f * lo.x);
            uint32_t k1 = score_key(m21 - 2.0f * lo.y);
            uint32_t k2 = score_key(m20 - 2.0f * hi.x);
            uint32_t k3 = score_key(m21 - 2.0f * hi.y);
            *(uint32_t*)(g_key + (size_t)rg0 * M_ROWS + cg) = k0 | (k1 << 16);
            *(uint32_t*)(g_key + (size_t)(rg0 + 8) * M_ROWS + cg) = k2 | (k3 << 16);
        }
    }
}

// ================= top-16 candidate SET per row (integer keys) =================
__global__ __launch_bounds__(512) void topk_kernel() {
    const int row  = blockIdx.x;
    const int tid  = threadIdx.x;
    const int lane = tid & 31;
    const int wid  = tid >> 5;
    const uint4* sr = (const uint4*)(g_key + (size_t)row * M_ROWS);

    uint32_t ld[4] = {0xFFFFFFFFu, 0xFFFFFFFFu, 0xFFFFFFFFu, 0xFFFFFFFFu};

    uint4 u[4];
    #pragma unroll
    for (int it = 0; it < 4; it++) u[it] = sr[it * 512 + tid];

    #pragma unroll
    for (int it = 0; it < 4; it++) {
        uint32_t m01 = __vminu2(u[it].x, u[it].y);
        uint32_t m23 = __vminu2(u[it].z, u[it].w);
        uint32_t m = __vminu2(m01, m23);
        uint32_t mm = min(m & 0xFFFFu, m >> 16);
        if ((mm << 14) <= ld[3]) {
            const uint32_t base = (uint32_t)(it * 512 + tid) * 8;
            uint32_t w[4] = {u[it].x, u[it].y, u[it].z, u[it].w};
            #pragma unroll
            for (int h = 0; h < 4; h++) {
                #pragma unroll
                for (int s = 0; s < 2; s++) {
                    uint32_t key = s ? (w[h] >> 16) : (w[h] & 0xFFFFu);
                    uint32_t v = (key << 14) | (base + h * 2 + s);
                    if (v < ld[3]) {
                        #pragma unroll
                        for (int k = 0; k < 4; k++) {
                            uint32_t a = min(ld[k], v);
                            v = max(ld[k], v);
                            ld[k] = a;
                        }
                    }
                }
            }
        }
    }

    __shared__ uint32_t wb[16][16];
    __shared__ int scout[K_CAND];

    #pragma unroll 1
    for (int r = 0; r < 16; r++) {
        uint32_t m = __reduce_min_sync(0xffffffffu, ld[0]);
        if (lane == 0) wb[wid][r] = m;
        if (ld[0] == m) {
            ld[0] = ld[1]; ld[1] = ld[2]; ld[2] = ld[3]; ld[3] = 0xFFFFFFFFu;
        }
    }
    __syncthreads();

    if (wid == 0) {
        uint32_t ed[8];
        #pragma unroll
        for (int j = 0; j < 8; j++) {
            int flat = lane * 8 + j;
            ed[j] = wb[flat >> 4][flat & 15];
        }
        #pragma unroll 1
        for (int r = 0; r < K_CAND; r++) {
            uint32_t v = ed[0];
            #pragma unroll
            for (int j = 1; j < 8; j++) v = min(v, ed[j]);
            uint32_t m = __reduce_min_sync(0xffffffffu, v);
            #pragma unroll
            for (int j = 0; j < 8; j++)
                if (ed[j] == m) ed[j] = 0xFFFFFFFFu;
            if (lane == 0) scout[r] = (int)(m & 0x3FFFu);
        }
        if (lane < K_CAND) g_cand[(size_t)row * K_CAND + lane] = scout[lane];
    }
}

// ================= exact rerank of 16 candidates (no atomics) =================
__global__ __launch_bounds__(512) void rerank_kernel(const float* __restrict__ feat,
                                                     const float* __restrict__ mem,
                                                     float* __restrict__ out) {
    const int row = blockIdx.x;
    const int wid = threadIdx.x >> 5;
    const int lid = threadIdx.x & 31;

    __shared__ float sd[K_CAND];
    __shared__ int   si[K_CAND];

    int cand = g_cand[(size_t)row * K_CAND + wid];
    const float4* f4 = (const float4*)(feat + (size_t)row * D_DIM);
    const float4* m4 = (const float4*)(mem + (size_t)cand * D_DIM);
    float acc = 0.0f;
    #pragma unroll
    for (int i = 0; i < 4; i++) {
        float4 a = f4[lid + i * 32];
        float4 b = m4[lid + i * 32];
        acc += a.x * b.x + a.y * b.y + a.z * b.z + a.w * b.w;
    }
    #pragma unroll
    for (int o = 16; o; o >>= 1) acc += __shfl_down_sync(0xffffffffu, acc, o);
    if (lid == 0) {
        float d2 = g_x2[row] + g_m2[cand] - 2.0f * acc;
        sd[wid] = sqrtf(fmaxf(d2, 0.0f) + EPSF);
        si[wid] = cand;
    }
    __syncthreads();

    if (threadIdx.x == 0) {
        for (int i = 1; i < K_CAND; i++) {
            float d = sd[i]; int ix = si[i];
            int j = i - 1;
            while (j >= 0 && (sd[j] > d || (sd[j] == d && si[j] > ix))) {
                sd[j + 1] = sd[j]; si[j + 1] = si[j]; j--;
            }
            sd[j + 1] = d; si[j + 1] = ix;
        }
        float* knn_out = out + 2 * (size_t)N_ROWS * D_DIM + (size_t)row * K_TOP;
        float sum = 0.0f;
        #pragma unroll
        for (int k = 0; k < K_TOP; k++) { knn_out[k] = sd[k]; sum += sd[k]; }
        g_idx0[row] = si[0];
        g_mean[row] = sum * 0.1f;
    }
}

// ================= single-block min/max reduction over g_mean =================
__global__ __launch_bounds__(1024) void reduce_minmax() {
    const int tid = threadIdx.x;
    float mn = FLT_MAX, mx = -FLT_MAX;
    #pragma unroll
    for (int i = 0; i < N_ROWS / 1024; i++) {
        float v = g_mean[tid + i * 1024];
        mn = fminf(mn, v);
        mx = fmaxf(mx, v);
    }
    #pragma unroll
    for (int o = 16; o; o >>= 1) {
        mn = fminf(mn, __shfl_down_sync(0xffffffffu, mn, o));
        mx = fmaxf(mx, __shfl_down_sync(0xffffffffu, mx, o));
    }
    __shared__ float smn[32], smx[32];
    if ((tid & 31) == 0) { smn[tid >> 5] = mn; smx[tid >> 5] = mx; }
    __syncthreads();
    if (tid < 32) {
        mn = smn[tid]; mx = smx[tid];
        #pragma unroll
        for (int o = 16; o; o >>= 1) {
            mn = fminf(mn, __shfl_down_sync(0xffffffffu, mn, o));
            mx = fmaxf(mx, __shfl_down_sync(0xffffffffu, mx, o));
        }
        if (tid == 0) { g_dmin = mn; g_dmax = mx; }
    }
}

// ================= final epilogue =================
__global__ __launch_bounds__(128) void final_kernel(const float* __restrict__ feat,
                                                    const float* __restrict__ mem,
                                                    const float* __restrict__ iscale,
                                                    const float* __restrict__ dscale,
                                                    float* __restrict__ out) {
    const int row = blockIdx.x;
    const int t = threadIdx.x;

    const float* knn = out + 2 * (size_t)N_ROWS * D_DIM;
    float norm = knn[(size_t)row * K_TOP] + EPSF;
    float inv = 1.0f / norm;
    int idx0 = g_idx0[row];

    float4 f  = *(const float4*)(feat + (size_t)row * D_DIM + t * 4);
    float4 nb = *(const float4*)(mem + (size_t)idx0 * D_DIM + t * 4);

    float v0 = fabsf((f.x - nb.x) * inv);
    float v1 = fabsf((f.y - nb.y) * inv);
    float v2 = fabsf((f.z - nb.z) * inv);
    float v3 = fabsf((f.w - nb.w) * inv);

    float mn = fminf(fminf(v0, v1), fminf(v2, v3));
    float mx = fmaxf(fmaxf(v0, v1), fmaxf(v2, v3));
    #pragma unroll
    for (int o = 16; o; o >>= 1) {
        mn = fminf(mn, __shfl_down_sync(0xffffffffu, mn, o));
        mx = fmaxf(mx, __shfl_down_sync(0xffffffffu, mx, o));
    }
    __shared__ float smn[4], smx[4];
    __shared__ float bmn, bmx;
    if ((t & 31) == 0) { smn[t >> 5] = mn; smx[t >> 5] = mx; }
    __syncthreads();
    if (t == 0) {
        bmn = fminf(fminf(smn[0], smn[1]), fminf(smn[2], smn[3]));
        bmx = fmaxf(fmaxf(smx[0], smx[1]), fmaxf(smx[2], smx[3]));
    }
    __syncthreads();
    float inf_min = bmn;
    float rinv = 1.0f / (bmx - inf_min + EPSF);

    float dn = (g_mean[row] - g_dmin) / (g_dmax - g_dmin + EPSF);

    float si = iscale[0], sd = dscale[0];
    float base = sd * dn - 0.5f;

    *(float4*)(out + (size_t)row * D_DIM + t * 4) = make_float4(v0, v1, v2, v3);

    float4 ns;
    float c;
    c = si * ((v0 - inf_min) * rinv) + base; ns.x = 0.01f + 0.49f / (1.0f + expf(-c));
    c = si * ((v1 - inf_min) * rinv) + base; ns.y = 0.01f + 0.49f / (1.0f + expf(-c));
    c = si * ((v2 - inf_min) * rinv) + base; ns.z = 0.01f + 0.49f / (1.0f + expf(-c));
    c = si * ((v3 - inf_min) * rinv) + base; ns.w = 0.01f + 0.49f / (1.0f + expf(-c));
    *(float4*)(out + (size_t)N_ROWS * D_DIM + (size_t)row * D_DIM + t * 4) = ns;
}

// ================= launch =================
extern "C" void kernel_launch(void* const* d_in, const int* in_sizes, int n_in,
                              void* d_out, int out_size) {
    const float* feat = (const float*)d_in[0];
    const float* mem  = (const float*)d_in[1];
    const float* isc  = (const float*)d_in[2];
    const float* dsc  = (const float*)d_in[3];
    float* out = (float*)d_out;

    cudaFuncSetAttribute(gemm_score_mma, cudaFuncAttributeMaxDynamicSharedMemorySize, SM_TOT);

    rowsumsq_conv<<<N_ROWS, 128>>>(feat, 0);
    rowsumsq_conv<<<M_ROWS, 128>>>(mem, 1);

    dim3 ggrid(M_ROWS / 128, N_ROWS / 128);  // (128, 64)
    gemm_score_mma<<<ggrid, 128, SM_TOT>>>();

    topk_kernel<<<N_ROWS, 512>>>();
    rerank_kernel<<<N_ROWS, 512>>>(feat, mem, out);
    reduce_minmax<<<1, 1024>>>();
    final_kernel<<<N_ROWS, 128>>>(feat, mem, isc, dsc, out);
}

// round 16
// speedup vs baseline: 1.0219x; 1.0219x over previous
#include <cuda_runtime.h>
#include <cuda_fp16.h>
#include <cuda_bf16.h>
#include <math.h>
#include <float.h>
#include <stdint.h>

#define N_ROWS 8192
#define M_ROWS 16384
#define D_DIM  512
#define K_TOP  10
#define K_CAND 16
#define EPSF   1e-8f

// ================= helpers =================
__device__ __forceinline__ uint32_t smem_u32(const void* p) {
    uint32_t a;
    asm("{ .reg .u64 t; cvta.to.shared.u64 t, %1; cvt.u32.u64 %0, t; }" : "=r"(a) : "l"(p));
    return a;
}
#define CP_ASYNC16(dst, src) asm volatile("cp.async.cg.shared.global [%0], [%1], 16;" :: "r"(dst), "l"(src) : "memory")
#define CP_COMMIT()          asm volatile("cp.async.commit_group;" ::: "memory")
#define CP_WAIT(n)           asm volatile("cp.async.wait_group %0;" :: "n"(n) : "memory")

#define LDSM_X4(r0, r1, r2, r3, a) \
    asm volatile("ldmatrix.sync.aligned.m8n8.x4.shared.b16 {%0,%1,%2,%3}, [%4];" \
        : "=r"(r0), "=r"(r1), "=r"(r2), "=r"(r3) : "r"(a))

// fp16 in, fp16 accumulate: D/C are 2x half2 regs
#define MMA16816_F16(c0, c1, a0, a1, a2, a3, b0, b1) \
    asm volatile("mma.sync.aligned.m16n8k16.row.col.f16.f16.f16.f16 " \
        "{%0,%1}, {%2,%3,%4,%5}, {%6,%7}, {%0,%1};" \
        : "+r"(c0), "+r"(c1) \
        : "r"(a0), "r"(a1), "r"(a2), "r"(a3), "r"(b0), "r"(b1))

// monotone u16 key from float (via bf16): order-preserving, smaller = nearer
__device__ __forceinline__ uint32_t score_key(float s) {
    uint16_t bits = __bfloat16_as_ushort(__float2bfloat16(s));
    uint16_t key = (bits & 0x8000) ? (uint16_t)~bits : (uint16_t)(bits | 0x8000);
    return (uint32_t)key;
}

// ================= device scratch =================
__device__ uint16_t g_key[(size_t)N_ROWS * (size_t)M_ROWS];  // 256 MB u16 key matrix
__device__ __half g_ah[(size_t)N_ROWS * D_DIM];
__device__ __half g_bh[(size_t)M_ROWS * D_DIM];
__device__ float g_x2[N_ROWS];
__device__ float g_m2[M_ROWS];
__device__ float g_mean[N_ROWS];
__device__ int   g_idx0[N_ROWS];
__device__ int   g_cand[(size_t)N_ROWS * K_CAND];
__device__ float g_dmin;
__device__ float g_dmax;

// ================= fused: row sum-of-squares + fp32->fp16 convert =================
__global__ __launch_bounds__(128) void rowsumsq_conv(const float* __restrict__ src, int which) {
    float* dst = which ? g_m2 : g_x2;
    __half* hout = which ? g_bh : g_ah;
    int row = blockIdx.x;
    const float4* p = (const float4*)(src + (size_t)row * D_DIM);
    float4 v = p[threadIdx.x];

    __half2 h01 = __floats2half2_rn(v.x, v.y);
    __half2 h23 = __floats2half2_rn(v.z, v.w);
    __half2* ho = (__half2*)(hout + (size_t)row * D_DIM) + threadIdx.x * 2;
    ho[0] = h01; ho[1] = h23;

    float s = v.x * v.x + v.y * v.y + v.z * v.z + v.w * v.w;
    #pragma unroll
    for (int o = 16; o; o >>= 1) s += __shfl_down_sync(0xffffffffu, s, o);
    __shared__ float ws[4];
    if ((threadIdx.x & 31) == 0) ws[threadIdx.x >> 5] = s;
    __syncthreads();
    if (threadIdx.x == 0) dst[row] = ws[0] + ws[1] + ws[2] + ws[3];
}

// ================= fp16 HMMA GEMM (fp16 acc) -> u16 key matrix =================
// R14 config (best measured): 128x256 CTA tile, BK=64, 256 threads = 8 warps
// (2m x 4n), warp tile 64x64. 2-stage double buffer -> 110.6 KB -> 2 CTAs/SM.
#define ROWB    144
#define SA_STG  (128 * ROWB)
#define SB_STG  (256 * ROWB)
#define SB_BASE (2 * SA_STG)
#define SM_TOT  (2 * SA_STG + 2 * SB_STG)  // 110592

__global__ void __launch_bounds__(256, 2) gemm_score_mma() {
    extern __shared__ __align__(128) uint8_t smem[];
    const uint32_t sbA = smem_u32(smem);
    const uint32_t sbB = sbA + SB_BASE;

    const int tid  = threadIdx.x;
    const int lane = tid & 31;
    const int wid  = tid >> 5;
    const int wm   = wid >> 2;
    const int wn   = wid & 3;
    const int bm   = blockIdx.y * 128;
    const int bn   = blockIdx.x * 256;

    const int rr = tid >> 3;
    const int kc = tid & 7;
    const __half* gA = g_ah + (size_t)bm * D_DIM + kc * 8;
    const __half* gB = g_bh + (size_t)bn * D_DIM + kc * 8;

    const int lrow = (lane & 7) + ((lane >> 3) & 1) * 8;
    const int lcol = (lane >> 4) * 8;
    uint32_t aBase[4], bBase[4];
    #pragma unroll
    for (int mf = 0; mf < 4; mf++)
        aBase[mf] = sbA + (wm * 64 + mf * 16 + lrow) * ROWB + lcol * 2;
    #pragma unroll
    for (int np = 0; np < 4; np++)
        bBase[np] = sbB + (wn * 64 + np * 16 + lrow) * ROWB + lcol * 2;

    uint32_t acc[4][8][2];
    #pragma unroll
    for (int mf = 0; mf < 4; mf++)
        #pragma unroll
        for (int nf = 0; nf < 8; nf++) { acc[mf][nf][0] = 0u; acc[mf][nf][1] = 0u; }

    auto load_stage = [&](int kt, int buf) {
        const int koff = kt * 64;
        #pragma unroll
        for (int i = 0; i < 4; i++) {
            int r = rr + i * 32;
            CP_ASYNC16(sbA + buf * SA_STG + r * ROWB + kc * 16,
                       gA + (size_t)r * D_DIM + koff);
        }
        #pragma unroll
        for (int i = 0; i < 8; i++) {
            int r = rr + i * 32;
            CP_ASYNC16(sbB + buf * SB_STG + r * ROWB + kc * 16,
                       gB + (size_t)r * D_DIM + koff);
        }
    };

    load_stage(0, 0); CP_COMMIT();

    #pragma unroll 1
    for (int kt = 0; kt < 8; kt++) {
        const int buf = kt & 1;
        CP_WAIT(0);
        __syncthreads();

        if (kt + 1 < 8) {
            load_stage(kt + 1, buf ^ 1);
            CP_COMMIT();
        }

        const uint32_t ao = buf * SA_STG;
        const uint32_t bo = buf * SB_STG;

        #pragma unroll
        for (int ks = 0; ks < 4; ks++) {
            const int ko = ks * 32;
            uint32_t af[4][4], bf[4][4];
            #pragma unroll
            for (int mf = 0; mf < 4; mf++)
                LDSM_X4(af[mf][0], af[mf][1], af[mf][2], af[mf][3], aBase[mf] + ao + ko);
            #pragma unroll
            for (int np = 0; np < 4; np++)
                LDSM_X4(bf[np][0], bf[np][1], bf[np][2], bf[np][3], bBase[np] + bo + ko);

            #pragma unroll
            for (int mf = 0; mf < 4; mf++) {
                #pragma unroll
                for (int nf = 0; nf < 8; nf++) {
                    const int np = nf >> 1, o = nf & 1;
                    MMA16816_F16(acc[mf][nf][0], acc[mf][nf][1],
                                 af[mf][0], af[mf][1], af[mf][2], af[mf][3],
                                 bf[np][0 + o], bf[np][2 + o]);
                }
            }
        }
    }

    // epilogue: key = monotone_u16(m2 - 2*dot), packed 2 per u32
    const int q = lane >> 2, p = lane & 3;
    #pragma unroll
    for (int nf = 0; nf < 8; nf++) {
        const int cg = bn + wn * 64 + nf * 8 + p * 2;
        const float m20 = g_m2[cg], m21 = g_m2[cg + 1];
        #pragma unroll
        for (int mf = 0; mf < 4; mf++) {
            const int rg0 = bm + wm * 64 + mf * 16 + q;
            float2 lo = __half22float2(*(const __half2*)&acc[mf][nf][0]);
            float2 hi = __half22float2(*(const __half2*)&acc[mf][nf][1]);
            uint32_t k0 = score_key(m20 - 2.0f * lo.x);
            uint32_t k1 = score_key(m21 - 2.0f * lo.y);
            uint32_t k2 = score_key(m20 - 2.0f * hi.x);
            uint32_t k3 = score_key(m21 - 2.0f * hi.y);
            *(uint32_t*)(g_key + (size_t)rg0 * M_ROWS + cg) = k0 | (k1 << 16);
            *(uint32_t*)(g_key + (size_t)(rg0 + 8) * M_ROWS + cg) = k2 | (k3 << 16);
        }
    }
}

// ================= top-16 candidate SET per row (integer keys) =================
// Guard 16 elements at a time: 7-op vminu2 tree + one packed threshold compare.
__global__ __launch_bounds__(512) void topk_kernel() {
    const int row  = blockIdx.x;
    const int tid  = threadIdx.x;
    const int lane = tid & 31;
    const int wid  = tid >> 5;
    const uint4* sr = (const uint4*)(g_key + (size_t)row * M_ROWS);

    uint32_t ld[4] = {0xFFFFFFFFu, 0xFFFFFFFFu, 0xFFFFFFFFu, 0xFFFFFFFFu};
    uint32_t thr2 = 0xFFFFFFFFu;  // packed dup of current cutoff key (ld[3]>>14)

    uint4 u[4];
    #pragma unroll
    for (int it = 0; it < 4; it++) u[it] = sr[it * 512 + tid];

    #pragma unroll
    for (int it = 0; it < 4; it += 2) {
        // vmin tree over 8 u32 = 16 keys
        uint32_t a0 = __vminu2(u[it].x, u[it].y);
        uint32_t a1 = __vminu2(u[it].z, u[it].w);
        uint32_t a2 = __vminu2(u[it + 1].x, u[it + 1].y);
        uint32_t a3 = __vminu2(u[it + 1].z, u[it + 1].w);
        uint32_t b0 = __vminu2(a0, a1);
        uint32_t b1 = __vminu2(a2, a3);
        uint32_t m  = __vminu2(b0, b1);
        // any halfword of m strictly below cutoff? (__vsetltu2: 1 per winning half)
        if (__vcmpltu2(m, thr2)) {
            #pragma unroll
            for (int half = 0; half < 2; half++) {
                const uint4 uu = half ? u[it + 1] : u[it];
                const uint32_t base = (uint32_t)((it + half) * 512 + tid) * 8;
                uint32_t w[4] = {uu.x, uu.y, uu.z, uu.w};
                #pragma unroll
                for (int h = 0; h < 4; h++) {
                    #pragma unroll
                    for (int s = 0; s < 2; s++) {
                        uint32_t key = s ? (w[h] >> 16) : (w[h] & 0xFFFFu);
                        uint32_t v = (key << 14) | (base + h * 2 + s);
                        if (v < ld[3]) {
                            #pragma unroll
                            for (int k = 0; k < 4; k++) {
                                uint32_t a = min(ld[k], v);
                                v = max(ld[k], v);
                                ld[k] = a;
                            }
                        }
                    }
                }
            }
            uint32_t ck = ld[3] >> 14;
            thr2 = ck | (ck << 16);
        }
    }

    __shared__ uint32_t wb[16][16];
    __shared__ int scout[K_CAND];

    #pragma unroll 1
    for (int r = 0; r < 16; r++) {
        uint32_t m = __reduce_min_sync(0xffffffffu, ld[0]);
        if (lane == 0) wb[wid][r] = m;
        if (ld[0] == m) {
            ld[0] = ld[1]; ld[1] = ld[2]; ld[2] = ld[3]; ld[3] = 0xFFFFFFFFu;
        }
    }
    __syncthreads();

    if (wid == 0) {
        uint32_t ed[8];
        #pragma unroll
        for (int j = 0; j < 8; j++) {
            int flat = lane * 8 + j;
            ed[j] = wb[flat >> 4][flat & 15];
        }
        #pragma unroll 1
        for (int r = 0; r < K_CAND; r++) {
            uint32_t v = ed[0];
            #pragma unroll
            for (int j = 1; j < 8; j++) v = min(v, ed[j]);
            uint32_t m = __reduce_min_sync(0xffffffffu, v);
            #pragma unroll
            for (int j = 0; j < 8; j++)
                if (ed[j] == m) ed[j] = 0xFFFFFFFFu;
            if (lane == 0) scout[r] = (int)(m & 0x3FFFu);
        }
        if (lane < K_CAND) g_cand[(size_t)row * K_CAND + lane] = scout[lane];
    }
}

// ================= exact rerank of 16 candidates (no atomics) =================
__global__ __launch_bounds__(512) void rerank_kernel(const float* __restrict__ feat,
                                                     const float* __restrict__ mem,
                                                     float* __restrict__ out) {
    const int row = blockIdx.x;
    const int wid = threadIdx.x >> 5;
    const int lid = threadIdx.x & 31;

    __shared__ float sd[K_CAND];
    __shared__ int   si[K_CAND];

    int cand = g_cand[(size_t)row * K_CAND + wid];
    const float4* f4 = (const float4*)(feat + (size_t)row * D_DIM);
    const float4* m4 = (const float4*)(mem + (size_t)cand * D_DIM);
    float acc = 0.0f;
    #pragma unroll
    for (int i = 0; i < 4; i++) {
        float4 a = f4[lid + i * 32];
        float4 b = m4[lid + i * 32];
        acc += a.x * b.x + a.y * b.y + a.z * b.z + a.w * b.w;
    }
    #pragma unroll
    for (int o = 16; o; o >>= 1) acc += __shfl_down_sync(0xffffffffu, acc, o);
    if (lid == 0) {
        float d2 = g_x2[row] + g_m2[cand] - 2.0f * acc;
        sd[wid] = sqrtf(fmaxf(d2, 0.0f) + EPSF);
        si[wid] = cand;
    }
    __syncthreads();

    if (threadIdx.x == 0) {
        for (int i = 1; i < K_CAND; i++) {
            float d = sd[i]; int ix = si[i];
            int j = i - 1;
            while (j >= 0 && (sd[j] > d || (sd[j] == d && si[j] > ix))) {
                sd[j + 1] = sd[j]; si[j + 1] = si[j]; j--;
            }
            sd[j + 1] = d; si[j + 1] = ix;
        }
        float* knn_out = out + 2 * (size_t)N_ROWS * D_DIM + (size_t)row * K_TOP;
        float sum = 0.0f;
        #pragma unroll
        for (int k = 0; k < K_TOP; k++) { knn_out[k] = sd[k]; sum += sd[k]; }
        g_idx0[row] = si[0];
        g_mean[row] = sum * 0.1f;
    }
}

// ================= single-block min/max reduction over g_mean =================
__global__ __launch_bounds__(1024) void reduce_minmax() {
    const int tid = threadIdx.x;
    float mn = FLT_MAX, mx = -FLT_MAX;
    #pragma unroll
    for (int i = 0; i < N_ROWS / 1024; i++) {
        float v = g_mean[tid + i * 1024];
        mn = fminf(mn, v);
        mx = fmaxf(mx, v);
    }
    #pragma unroll
    for (int o = 16; o; o >>= 1) {
        mn = fminf(mn, __shfl_down_sync(0xffffffffu, mn, o));
        mx = fmaxf(mx, __shfl_down_sync(0xffffffffu, mx, o));
    }
    __shared__ float smn[32], smx[32];
    if ((tid & 31) == 0) { smn[tid >> 5] = mn; smx[tid >> 5] = mx; }
    __syncthreads();
    if (tid < 32) {
        mn = smn[tid]; mx = smx[tid];
        #pragma unroll
        for (int o = 16; o; o >>= 1) {
            mn = fminf(mn, __shfl_down_sync(0xffffffffu, mn, o));
            mx = fmaxf(mx, __shfl_down_sync(0xffffffffu, mx, o));
        }
        if (tid == 0) { g_dmin = mn; g_dmax = mx; }
    }
}

// ================= final epilogue =================
__global__ __launch_bounds__(128) void final_kernel(const float* __restrict__ feat,
                                                    const float* __restrict__ mem,
                                                    const float* __restrict__ iscale,
                                                    const float* __restrict__ dscale,
                                                    float* __restrict__ out) {
    const int row = blockIdx.x;
    const int t = threadIdx.x;

    const float* knn = out + 2 * (size_t)N_ROWS * D_DIM;
    float norm = knn[(size_t)row * K_TOP] + EPSF;
    float inv = 1.0f / norm;
    int idx0 = g_idx0[row];

    float4 f  = *(const float4*)(feat + (size_t)row * D_DIM + t * 4);
    float4 nb = *(const float4*)(mem + (size_t)idx0 * D_DIM + t * 4);

    float v0 = fabsf((f.x - nb.x) * inv);
    float v1 = fabsf((f.y - nb.y) * inv);
    float v2 = fabsf((f.z - nb.z) * inv);
    float v3 = fabsf((f.w - nb.w) * inv);

    float mn = fminf(fminf(v0, v1), fminf(v2, v3));
    float mx = fmaxf(fmaxf(v0, v1), fmaxf(v2, v3));
    #pragma unroll
    for (int o = 16; o; o >>= 1) {
        mn = fminf(mn, __shfl_down_sync(0xffffffffu, mn, o));
        mx = fmaxf(mx, __shfl_down_sync(0xffffffffu, mx, o));
    }
    __shared__ float smn[4], smx[4];
    __shared__ float bmn, bmx;
    if ((t & 31) == 0) { smn[t >> 5] = mn; smx[t >> 5] = mx; }
    __syncthreads();
    if (t == 0) {
        bmn = fminf(fminf(smn[0], smn[1]), fminf(smn[2], smn[3]));
        bmx = fmaxf(fmaxf(smx[0], smx[1]), fmaxf(smx[2], smx[3]));
    }
    __syncthreads();
    float inf_min = bmn;
    float rinv = 1.0f / (bmx - inf_min + EPSF);

    float dn = (g_mean[row] - g_dmin) / (g_dmax - g_dmin + EPSF);

    float si = iscale[0], sd = dscale[0];
    float base = sd * dn - 0.5f;

    *(float4*)(out + (size_t)row * D_DIM + t * 4) = make_float4(v0, v1, v2, v3);

    float4 ns;
    float c;
    c = si * ((v0 - inf_min) * rinv) + base; ns.x = 0.01f + 0.49f / (1.0f + expf(-c));
    c = si * ((v1 - inf_min) * rinv) + base; ns.y = 0.01f + 0.49f / (1.0f + expf(-c));
    c = si * ((v2 - inf_min) * rinv) + base; ns.z = 0.01f + 0.49f / (1.0f + expf(-c));
    c = si * ((v3 - inf_min) * rinv) + base; ns.w = 0.01f + 0.49f / (1.0f + expf(-c));
    *(float4*)(out + (size_t)N_ROWS * D_DIM + (size_t)row * D_DIM + t * 4) = ns;
}

// ================= launch =================
extern "C" void kernel_launch(void* const* d_in, const int* in_sizes, int n_in,
                              void* d_out, int out_size) {
    const float* feat = (const float*)d_in[0];
    const float* mem  = (const float*)d_in[1];
    const float* isc  = (const float*)d_in[2];
    const float* dsc  = (const float*)d_in[3];
    float* out = (float*)d_out;

    cudaFuncSetAttribute(gemm_score_mma, cudaFuncAttributeMaxDynamicSharedMemorySize, SM_TOT);

    rowsumsq_conv<<<N_ROWS, 128>>>(feat, 0);
    rowsumsq_conv<<<M_ROWS, 128>>>(mem, 1);

    dim3 ggrid(M_ROWS / 256, N_ROWS / 128);  // (64, 64)
    gemm_score_mma<<<ggrid, 256, SM_TOT>>>();

    topk_kernel<<<N_ROWS, 512>>>();
    rerank_kernel<<<N_ROWS, 512>>>(feat, mem, out);
    reduce_minmax<<<1, 1024>>>();
    final_kernel<<<N_ROWS, 128>>>(feat, mem, isc, dsc, out);
}

// round 17
// speedup vs baseline: 1.0453x; 1.0229x over previous
#include <cuda_runtime.h>
#include <cuda_fp16.h>
#include <cuda_bf16.h>
#include <math.h>
#include <float.h>
#include <stdint.h>

#define N_ROWS 8192
#define M_ROWS 16384
#define D_DIM  512
#define K_TOP  10
#define K_CAND 16
#define EPSF   1e-8f

// ================= helpers =================
__device__ __forceinline__ uint32_t smem_u32(const void* p) {
    uint32_t a;
    asm("{ .reg .u64 t; cvta.to.shared.u64 t, %1; cvt.u32.u64 %0, t; }" : "=r"(a) : "l"(p));
    return a;
}
#define CP_ASYNC16(dst, src) asm volatile("cp.async.cg.shared.global [%0], [%1], 16;" :: "r"(dst), "l"(src) : "memory")
#define CP_COMMIT()          asm volatile("cp.async.commit_group;" ::: "memory")
#define CP_WAIT(n)           asm volatile("cp.async.wait_group %0;" :: "n"(n) : "memory")

#define LDSM_X4(r0, r1, r2, r3, a) \
    asm volatile("ldmatrix.sync.aligned.m8n8.x4.shared.b16 {%0,%1,%2,%3}, [%4];" \
        : "=r"(r0), "=r"(r1), "=r"(r2), "=r"(r3) : "r"(a))

// fp16 in, fp16 accumulate: D/C are 2x half2 regs
#define MMA16816_F16(c0, c1, a0, a1, a2, a3, b0, b1) \
    asm volatile("mma.sync.aligned.m16n8k16.row.col.f16.f16.f16.f16 " \
        "{%0,%1}, {%2,%3,%4,%5}, {%6,%7}, {%0,%1};" \
        : "+r"(c0), "+r"(c1) \
        : "r"(a0), "r"(a1), "r"(a2), "r"(a3), "r"(b0), "r"(b1))

// monotone u16 key from float (via bf16): order-preserving, smaller = nearer
__device__ __forceinline__ uint32_t score_key(float s) {
    uint16_t bits = __bfloat16_as_ushort(__float2bfloat16(s));
    uint16_t key = (bits & 0x8000) ? (uint16_t)~bits : (uint16_t)(bits | 0x8000);
    return (uint32_t)key;
}

// ================= device scratch =================
__device__ uint16_t g_key[(size_t)N_ROWS * (size_t)M_ROWS];  // 256 MB u16 key matrix
__device__ __half g_ah[(size_t)N_ROWS * D_DIM];
__device__ __half g_bh[(size_t)M_ROWS * D_DIM];
__device__ float g_x2[N_ROWS];
__device__ float g_m2[M_ROWS];
__device__ float g_mean[N_ROWS];
__device__ int   g_idx0[N_ROWS];
__device__ int   g_cand[(size_t)N_ROWS * K_CAND];
__device__ float g_dmin;
__device__ float g_dmax;

// ================= fused: row sum-of-squares + fp32->fp16 convert =================
__global__ __launch_bounds__(128) void rowsumsq_conv(const float* __restrict__ src, int which) {
    float* dst = which ? g_m2 : g_x2;
    __half* hout = which ? g_bh : g_ah;
    int row = blockIdx.x;
    const float4* p = (const float4*)(src + (size_t)row * D_DIM);
    float4 v = p[threadIdx.x];

    __half2 h01 = __floats2half2_rn(v.x, v.y);
    __half2 h23 = __floats2half2_rn(v.z, v.w);
    __half2* ho = (__half2*)(hout + (size_t)row * D_DIM) + threadIdx.x * 2;
    ho[0] = h01; ho[1] = h23;

    float s = v.x * v.x + v.y * v.y + v.z * v.z + v.w * v.w;
    #pragma unroll
    for (int o = 16; o; o >>= 1) s += __shfl_down_sync(0xffffffffu, s, o);
    __shared__ float ws[4];
    if ((threadIdx.x & 31) == 0) ws[threadIdx.x >> 5] = s;
    __syncthreads();
    if (threadIdx.x == 0) dst[row] = ws[0] + ws[1] + ws[2] + ws[3];
}

// ================= fp16 HMMA GEMM (fp16 acc) -> u16 key matrix =================
// R14 config (best measured): 128x256 CTA tile, BK=64, 256 threads = 8 warps
// (2m x 4n), warp tile 64x64. 2-stage double buffer -> 110.6 KB -> 2 CTAs/SM.
#define ROWB    144
#define SA_STG  (128 * ROWB)
#define SB_STG  (256 * ROWB)
#define SB_BASE (2 * SA_STG)
#define SM_TOT  (2 * SA_STG + 2 * SB_STG)  // 110592

__global__ void __launch_bounds__(256, 2) gemm_score_mma() {
    extern __shared__ __align__(128) uint8_t smem[];
    const uint32_t sbA = smem_u32(smem);
    const uint32_t sbB = sbA + SB_BASE;

    const int tid  = threadIdx.x;
    const int lane = tid & 31;
    const int wid  = tid >> 5;
    const int wm   = wid >> 2;
    const int wn   = wid & 3;
    const int bm   = blockIdx.y * 128;
    const int bn   = blockIdx.x * 256;

    const int rr = tid >> 3;
    const int kc = tid & 7;
    const __half* gA = g_ah + (size_t)bm * D_DIM + kc * 8;
    const __half* gB = g_bh + (size_t)bn * D_DIM + kc * 8;

    const int lrow = (lane & 7) + ((lane >> 3) & 1) * 8;
    const int lcol = (lane >> 4) * 8;
    uint32_t aBase[4], bBase[4];
    #pragma unroll
    for (int mf = 0; mf < 4; mf++)
        aBase[mf] = sbA + (wm * 64 + mf * 16 + lrow) * ROWB + lcol * 2;
    #pragma unroll
    for (int np = 0; np < 4; np++)
        bBase[np] = sbB + (wn * 64 + np * 16 + lrow) * ROWB + lcol * 2;

    uint32_t acc[4][8][2];
    #pragma unroll
    for (int mf = 0; mf < 4; mf++)
        #pragma unroll
        for (int nf = 0; nf < 8; nf++) { acc[mf][nf][0] = 0u; acc[mf][nf][1] = 0u; }

    auto load_stage = [&](int kt, int buf) {
        const int koff = kt * 64;
        #pragma unroll
        for (int i = 0; i < 4; i++) {
            int r = rr + i * 32;
            CP_ASYNC16(sbA + buf * SA_STG + r * ROWB + kc * 16,
                       gA + (size_t)r * D_DIM + koff);
        }
        #pragma unroll
        for (int i = 0; i < 8; i++) {
            int r = rr + i * 32;
            CP_ASYNC16(sbB + buf * SB_STG + r * ROWB + kc * 16,
                       gB + (size_t)r * D_DIM + koff);
        }
    };

    load_stage(0, 0); CP_COMMIT();

    #pragma unroll 1
    for (int kt = 0; kt < 8; kt++) {
        const int buf = kt & 1;
        CP_WAIT(0);
        __syncthreads();

        if (kt + 1 < 8) {
            load_stage(kt + 1, buf ^ 1);
            CP_COMMIT();
        }

        const uint32_t ao = buf * SA_STG;
        const uint32_t bo = buf * SB_STG;

        #pragma unroll
        for (int ks = 0; ks < 4; ks++) {
            const int ko = ks * 32;
            uint32_t af[4][4], bf[4][4];
            #pragma unroll
            for (int mf = 0; mf < 4; mf++)
                LDSM_X4(af[mf][0], af[mf][1], af[mf][2], af[mf][3], aBase[mf] + ao + ko);
            #pragma unroll
            for (int np = 0; np < 4; np++)
                LDSM_X4(bf[np][0], bf[np][1], bf[np][2], bf[np][3], bBase[np] + bo + ko);

            #pragma unroll
            for (int mf = 0; mf < 4; mf++) {
                #pragma unroll
                for (int nf = 0; nf < 8; nf++) {
                    const int np = nf >> 1, o = nf & 1;
                    MMA16816_F16(acc[mf][nf][0], acc[mf][nf][1],
                                 af[mf][0], af[mf][1], af[mf][2], af[mf][3],
                                 bf[np][0 + o], bf[np][2 + o]);
                }
            }
        }
    }

    // epilogue: key = monotone_u16(m2 - 2*dot), packed 2 per u32
    const int q = lane >> 2, p = lane & 3;
    #pragma unroll
    for (int nf = 0; nf < 8; nf++) {
        const int cg = bn + wn * 64 + nf * 8 + p * 2;
        const float m20 = g_m2[cg], m21 = g_m2[cg + 1];
        #pragma unroll
        for (int mf = 0; mf < 4; mf++) {
            const int rg0 = bm + wm * 64 + mf * 16 + q;
            float2 lo = __half22float2(*(const __half2*)&acc[mf][nf][0]);
            float2 hi = __half22float2(*(const __half2*)&acc[mf][nf][1]);
            uint32_t k0 = score_key(m20 - 2.0f * lo.x);
            uint32_t k1 = score_key(m21 - 2.0f * lo.y);
            uint32_t k2 = score_key(m20 - 2.0f * hi.x);
            uint32_t k3 = score_key(m21 - 2.0f * hi.y);
            *(uint32_t*)(g_key + (size_t)rg0 * M_ROWS + cg) = k0 | (k1 << 16);
            *(uint32_t*)(g_key + (size_t)(rg0 + 8) * M_ROWS + cg) = k2 | (k3 << 16);
        }
    }
}

// ================= top-16 candidate SET per row (integer keys) =================
// 256 threads, 16 elements/thread. Per-thread top-4; per-warp top-16 via REDUX
// (8 warps -> half the merge work of the 512-thread version); warp0 selects
// top-16 of 128 survivors.
__global__ __launch_bounds__(256) void topk_kernel() {
    const int row  = blockIdx.x;
    const int tid  = threadIdx.x;
    const int lane = tid & 31;
    const int wid  = tid >> 5;
    const uint4* sr = (const uint4*)(g_key + (size_t)row * M_ROWS);

    uint32_t ld[4] = {0xFFFFFFFFu, 0xFFFFFFFFu, 0xFFFFFFFFu, 0xFFFFFFFFu};

    uint4 u[8];
    #pragma unroll
    for (int it = 0; it < 8; it++) u[it] = sr[it * 256 + tid];

    #pragma unroll
    for (int it = 0; it < 8; it += 2) {
        uint32_t a0 = __vminu2(u[it].x, u[it].y);
        uint32_t a1 = __vminu2(u[it].z, u[it].w);
        uint32_t a2 = __vminu2(u[it + 1].x, u[it + 1].y);
        uint32_t a3 = __vminu2(u[it + 1].z, u[it + 1].w);
        uint32_t m  = __vminu2(__vminu2(a0, a1), __vminu2(a2, a3));
        uint32_t mm = min(m & 0xFFFFu, m >> 16);
        if ((mm << 14) <= ld[3]) {
            #pragma unroll
            for (int half = 0; half < 2; half++) {
                const uint4 uu = half ? u[it + 1] : u[it];
                const uint32_t base = (uint32_t)((it + half) * 256 + tid) * 8;
                uint32_t w[4] = {uu.x, uu.y, uu.z, uu.w};
                #pragma unroll
                for (int h = 0; h < 4; h++) {
                    #pragma unroll
                    for (int s = 0; s < 2; s++) {
                        uint32_t key = s ? (w[h] >> 16) : (w[h] & 0xFFFFu);
                        uint32_t v = (key << 14) | (base + h * 2 + s);
                        if (v < ld[3]) {
                            #pragma unroll
                            for (int k = 0; k < 4; k++) {
                                uint32_t a = min(ld[k], v);
                                v = max(ld[k], v);
                                ld[k] = a;
                            }
                        }
                    }
                }
            }
        }
    }

    __shared__ uint32_t wb[8][16];
    __shared__ int scout[K_CAND];

    // per-warp top-16 via REDUX min (8 warps)
    #pragma unroll 1
    for (int r = 0; r < 16; r++) {
        uint32_t m = __reduce_min_sync(0xffffffffu, ld[0]);
        if (lane == 0) wb[wid][r] = m;
        if (ld[0] == m) {
            ld[0] = ld[1]; ld[1] = ld[2]; ld[2] = ld[3]; ld[3] = 0xFFFFFFFFu;
        }
    }
    __syncthreads();

    // warp 0: top-16 of 128 survivors (4 per lane)
    if (wid == 0) {
        uint32_t ed[4];
        #pragma unroll
        for (int j = 0; j < 4; j++) {
            int flat = lane * 4 + j;
            ed[j] = wb[flat >> 4][flat & 15];
        }
        #pragma unroll 1
        for (int r = 0; r < K_CAND; r++) {
            uint32_t v = min(min(ed[0], ed[1]), min(ed[2], ed[3]));
            uint32_t m = __reduce_min_sync(0xffffffffu, v);
            #pragma unroll
            for (int j = 0; j < 4; j++)
                if (ed[j] == m) ed[j] = 0xFFFFFFFFu;
            if (lane == 0) scout[r] = (int)(m & 0x3FFFu);
        }
        if (lane < K_CAND) g_cand[(size_t)row * K_CAND + lane] = scout[lane];
    }
}

// ================= exact rerank of 16 candidates (no atomics) =================
__global__ __launch_bounds__(512) void rerank_kernel(const float* __restrict__ feat,
                                                     const float* __restrict__ mem,
                                                     float* __restrict__ out) {
    const int row = blockIdx.x;
    const int wid = threadIdx.x >> 5;
    const int lid = threadIdx.x & 31;

    __shared__ float sd[K_CAND];
    __shared__ int   si[K_CAND];

    int cand = g_cand[(size_t)row * K_CAND + wid];
    const float4* f4 = (const float4*)(feat + (size_t)row * D_DIM);
    const float4* m4 = (const float4*)(mem + (size_t)cand * D_DIM);
    float acc = 0.0f;
    #pragma unroll
    for (int i = 0; i < 4; i++) {
        float4 a = f4[lid + i * 32];
        float4 b = m4[lid + i * 32];
        acc += a.x * b.x + a.y * b.y + a.z * b.z + a.w * b.w;
    }
    #pragma unroll
    for (int o = 16; o; o >>= 1) acc += __shfl_down_sync(0xffffffffu, acc, o);
    if (lid == 0) {
        float d2 = g_x2[row] + g_m2[cand] - 2.0f * acc;
        sd[wid] = sqrtf(fmaxf(d2, 0.0f) + EPSF);
        si[wid] = cand;
    }
    __syncthreads();

    if (threadIdx.x == 0) {
        for (int i = 1; i < K_CAND; i++) {
            float d = sd[i]; int ix = si[i];
            int j = i - 1;
            while (j >= 0 && (sd[j] > d || (sd[j] == d && si[j] > ix))) {
                sd[j + 1] = sd[j]; si[j + 1] = si[j]; j--;
            }
            sd[j + 1] = d; si[j + 1] = ix;
        }
        float* knn_out = out + 2 * (size_t)N_ROWS * D_DIM + (size_t)row * K_TOP;
        float sum = 0.0f;
        #pragma unroll
        for (int k = 0; k < K_TOP; k++) { knn_out[k] = sd[k]; sum += sd[k]; }
        g_idx0[row] = si[0];
        g_mean[row] = sum * 0.1f;
    }
}

// ================= single-block min/max reduction over g_mean =================
__global__ __launch_bounds__(1024) void reduce_minmax() {
    const int tid = threadIdx.x;
    float mn = FLT_MAX, mx = -FLT_MAX;
    #pragma unroll
    for (int i = 0; i < N_ROWS / 1024; i++) {
        float v = g_mean[tid + i * 1024];
        mn = fminf(mn, v);
        mx = fmaxf(mx, v);
    }
    #pragma unroll
    for (int o = 16; o; o >>= 1) {
        mn = fminf(mn, __shfl_down_sync(0xffffffffu, mn, o));
        mx = fmaxf(mx, __shfl_down_sync(0xffffffffu, mx, o));
    }
    __shared__ float smn[32], smx[32];
    if ((tid & 31) == 0) { smn[tid >> 5] = mn; smx[tid >> 5] = mx; }
    __syncthreads();
    if (tid < 32) {
        mn = smn[tid]; mx = smx[tid];
        #pragma unroll
        for (int o = 16; o; o >>= 1) {
            mn = fminf(mn, __shfl_down_sync(0xffffffffu, mn, o));
            mx = fmaxf(mx, __shfl_down_sync(0xffffffffu, mx, o));
        }
        if (tid == 0) { g_dmin = mn; g_dmax = mx; }
    }
}

// ================= final epilogue =================
__global__ __launch_bounds__(128) void final_kernel(const float* __restrict__ feat,
                                                    const float* __restrict__ mem,
                                                    const float* __restrict__ iscale,
                                                    const float* __restrict__ dscale,
                                                    float* __restrict__ out) {
    const int row = blockIdx.x;
    const int t = threadIdx.x;

    const float* knn = out + 2 * (size_t)N_ROWS * D_DIM;
    float norm = knn[(size_t)row * K_TOP] + EPSF;
    float inv = 1.0f / norm;
    int idx0 = g_idx0[row];

    float4 f  = *(const float4*)(feat + (size_t)row * D_DIM + t * 4);
    float4 nb = *(const float4*)(mem + (size_t)idx0 * D_DIM + t * 4);

    float v0 = fabsf((f.x - nb.x) * inv);
    float v1 = fabsf((f.y - nb.y) * inv);
    float v2 = fabsf((f.z - nb.z) * inv);
    float v3 = fabsf((f.w - nb.w) * inv);

    float mn = fminf(fminf(v0, v1), fminf(v2, v3));
    float mx = fmaxf(fmaxf(v0, v1), fmaxf(v2, v3));
    #pragma unroll
    for (int o = 16; o; o >>= 1) {
        mn = fminf(mn, __shfl_down_sync(0xffffffffu, mn, o));
        mx = fmaxf(mx, __shfl_down_sync(0xffffffffu, mx, o));
    }
    __shared__ float smn[4], smx[4];
    __shared__ float bmn, bmx;
    if ((t & 31) == 0) { smn[t >> 5] = mn; smx[t >> 5] = mx; }
    __syncthreads();
    if (t == 0) {
        bmn = fminf(fminf(smn[0], smn[1]), fminf(smn[2], smn[3]));
        bmx = fmaxf(fmaxf(smx[0], smx[1]), fmaxf(smx[2], smx[3]));
    }
    __syncthreads();
    float inf_min = bmn;
    float rinv = 1.0f / (bmx - inf_min + EPSF);

    float dn = (g_mean[row] - g_dmin) / (g_dmax - g_dmin + EPSF);

    float si = iscale[0], sd = dscale[0];
    float base = sd * dn - 0.5f;

    *(float4*)(out + (size_t)row * D_DIM + t * 4) = make_float4(v0, v1, v2, v3);

    float4 ns;
    float c;
    c = si * ((v0 - inf_min) * rinv) + base; ns.x = 0.01f + 0.49f / (1.0f + expf(-c));
    c = si * ((v1 - inf_min) * rinv) + base; ns.y = 0.01f + 0.49f / (1.0f + expf(-c));
    c = si * ((v2 - inf_min) * rinv) + base; ns.z = 0.01f + 0.49f / (1.0f + expf(-c));
    c = si * ((v3 - inf_min) * rinv) + base; ns.w = 0.01f + 0.49f / (1.0f + expf(-c));
    *(float4*)(out + (size_t)N_ROWS * D_DIM + (size_t)row * D_DIM + t * 4) = ns;
}

// ================= launch =================
extern "C" void kernel_launch(void* const* d_in, const int* in_sizes, int n_in,
                              void* d_out, int out_size) {
    const float* feat = (const float*)d_in[0];
    const float* mem  = (const float*)d_in[1];
    const float* isc  = (const float*)d_in[2];
    const float* dsc  = (const float*)d_in[3];
    float* out = (float*)d_out;

    cudaFuncSetAttribute(gemm_score_mma, cudaFuncAttributeMaxDynamicSharedMemorySize, SM_TOT);

    rowsumsq_conv<<<N_ROWS, 128>>>(feat, 0);
    rowsumsq_conv<<<M_ROWS, 128>>>(mem, 1);

    dim3 ggrid(M_ROWS / 256, N_ROWS / 128);  // (64, 64)
    gemm_score_mma<<<ggrid, 256, SM_TOT>>>();

    topk_kernel<<<N_ROWS, 256>>>();
    rerank_kernel<<<N_ROWS, 512>>>(feat, mem, out);
    reduce_minmax<<<1, 1024>>>();
    final_kernel<<<N_ROWS, 128>>>(feat, mem, isc, dsc, out);
}